// round 12
// baseline (speedup 1.0000x reference)
#include <cuda_runtime.h>
#include <cuda_bf16.h>

#define Bn 4
#define Sn 4096
#define Hn 2048
#define H4 (Hn / 4)
#define EPSf 1e-6f

#define CS 16               // s-rows produced per block
#define NROWS (CS + 3)      // +3 causal halo

__device__ __forceinline__ float warp_sum(float v) {
#pragma unroll
    for (int o = 16; o; o >>= 1)
        v += __shfl_xor_sync(0xFFFFFFFFu, v, o);
    return v;
}

__device__ __forceinline__ float dot4(const float4 v) {
    return fmaf(v.x, v.x, fmaf(v.y, v.y, fmaf(v.z, v.z, v.w * v.w)));
}

// ---------------------------------------------------------------------------
// Fused RMSNorm + depthwise causal conv1d (K=4) + bias. One DRAM pass over x.
// grid = (S/CS, B) = 1024 blocks, block = 512, occ 2.  [R3 structure]
// Phase 1: 16 warps, full-row reductions (19 rows), uninterrupted 16-deep
//          LDG.128 streams. Halo window loads hoisted pre-barrier (overlap
//          with phase-1 streams; same-line MSHR merges).
// Phase 2: thread owns one float4 H-column, rolling 3-deep window; re-reads
//          via __ldcs (last-use, evict-first). Folded taps, streaming stores.
// ---------------------------------------------------------------------------
__global__ __launch_bounds__(512, 2) void fused_kernel(const float* __restrict__ x,
                                                       const float* __restrict__ nw,
                                                       const float* __restrict__ cw,
                                                       const float* __restrict__ cb,
                                                       float*       __restrict__ out) {
    __shared__ float s_ir[NROWS];

    const int b    = blockIdx.y;
    const int s0   = blockIdx.x * CS;
    const int tid  = threadIdx.x;
    const int warp = tid >> 5;
    const int lane = tid & 31;

    const float* xb = x   + (size_t)b * Sn * Hn;
    float*       ob = out + (size_t)b * Sn * Hn;

    // ---- Phase 1: per-row inv_rms for rows s0-3 .. s0+CS-1 (19 rows / 16 warps) ----
    for (int j = warp; j < NROWS; j += 16) {
        const int s = s0 - 3 + j;
        float a0 = 0.f, a1 = 0.f;
        if (s >= 0) {
            const float4* xr = reinterpret_cast<const float4*>(xb + (size_t)s * Hn);
#pragma unroll
            for (int i = 0; i < 16; i += 2) {
                float4 v0 = xr[lane + 32 * (i + 0)];
                float4 v1 = xr[lane + 32 * (i + 1)];
                a0 += dot4(v0);
                a1 += dot4(v1);
            }
        }
        float ss = warp_sum(a0 + a1);
        if (lane == 0)
            s_ir[j] = (s >= 0) ? rsqrtf(ss * (1.0f / (float)Hn) + EPSf) : 0.0f;
    }

    // ---- per-thread constants + PRE-BARRIER halo loads (overlap phase 1) ----
    const int h4 = tid;                 // 0..511
    const int h  = h4 * 4;

    const float4* cw4 = reinterpret_cast<const float4*>(cw);
    const float4 nwv = __ldg(&reinterpret_cast<const float4*>(nw)[h4]);
    float4 t0 = __ldg(&cw4[h + 0]);
    float4 t1 = __ldg(&cw4[h + 1]);
    float4 t2 = __ldg(&cw4[h + 2]);
    float4 t3 = __ldg(&cw4[h + 3]);
    t0.x *= nwv.x; t0.y *= nwv.x; t0.z *= nwv.x; t0.w *= nwv.x;
    t1.x *= nwv.y; t1.y *= nwv.y; t1.z *= nwv.y; t1.w *= nwv.y;
    t2.x *= nwv.z; t2.y *= nwv.z; t2.z *= nwv.z; t2.w *= nwv.z;
    t3.x *= nwv.w; t3.y *= nwv.w; t3.z *= nwv.w; t3.w *= nwv.w;
    const float4 bias = __ldg(&reinterpret_cast<const float4*>(cb)[h4]);

    // Halo raw values: loads are independent of s_ir, so issue them before the
    // barrier; they merge with phase-1's in-flight reads of the same lines.
    float4 hv[3];
#pragma unroll
    for (int j = 0; j < 3; j++) {
        const int s = s0 - 3 + j;
        hv[j] = (s >= 0)
              ? __ldcs(reinterpret_cast<const float4*>(xb + (size_t)s * Hn) + h4)
              : make_float4(0.f, 0.f, 0.f, 0.f);
    }

    __syncthreads();

    // ---- Phase 2: rolling-window conv over rows s0 .. s0+CS-1 ----
    float4 xm3, xm2, xm1;
    {
        const float r0 = s_ir[0], r1 = s_ir[1], r2 = s_ir[2];
        xm3.x = hv[0].x * r0; xm3.y = hv[0].y * r0; xm3.z = hv[0].z * r0; xm3.w = hv[0].w * r0;
        xm2.x = hv[1].x * r1; xm2.y = hv[1].y * r1; xm2.z = hv[1].z * r1; xm2.w = hv[1].w * r1;
        xm1.x = hv[2].x * r2; xm1.y = hv[2].y * r2; xm1.z = hv[2].z * r2; xm1.w = hv[2].w * r2;
    }

#pragma unroll 4
    for (int j = 0; j < CS; j++) {
        const int s = s0 + j;
        float4 v = __ldcs(reinterpret_cast<const float4*>(xb + (size_t)s * Hn) + h4);
        const float r = s_ir[j + 3];
        float4 xn;
        xn.x = v.x * r;
        xn.y = v.y * r;
        xn.z = v.z * r;
        xn.w = v.w * r;

        float4 y;
        y.x = fmaf(t0.x, xm3.x, fmaf(t0.y, xm2.x, fmaf(t0.z, xm1.x, fmaf(t0.w, xn.x, bias.x))));
        y.y = fmaf(t1.x, xm3.y, fmaf(t1.y, xm2.y, fmaf(t1.z, xm1.y, fmaf(t1.w, xn.y, bias.y))));
        y.z = fmaf(t2.x, xm3.z, fmaf(t2.y, xm2.z, fmaf(t2.z, xm1.z, fmaf(t2.w, xn.z, bias.z))));
        y.w = fmaf(t3.x, xm3.w, fmaf(t3.y, xm2.w, fmaf(t3.z, xm1.w, fmaf(t3.w, xn.w, bias.w))));

        // Streaming store: output is never re-read; don't pollute L2.
        __stcs(reinterpret_cast<float4*>(ob + (size_t)s * Hn) + h4, y);

        xm3 = xm2; xm2 = xm1; xm1 = xn;
    }
}

// ---------------------------------------------------------------------------
// Inputs (metadata order): hidden_states, norm_weight, conv_weight, conv_bias
// ---------------------------------------------------------------------------
extern "C" void kernel_launch(void* const* d_in, const int* in_sizes, int n_in,
                              void* d_out, int out_size) {
    const float* x  = (const float*)d_in[0];
    const float* nw = (const float*)d_in[1];
    const float* cw = (const float*)d_in[2];
    const float* cb = (const float*)d_in[3];
    float* out = (float*)d_out;

    dim3 grid(Sn / CS, Bn);             // (256, 4) = 1024 blocks
    fused_kernel<<<grid, 512>>>(x, nw, cw, cb, out);
}

// round 13
// speedup vs baseline: 1.0513x; 1.0513x over previous
#include <cuda_runtime.h>
#include <cuda_bf16.h>

#define Bn 4
#define Sn 4096
#define Hn 2048
#define EPSf 1e-6f

#define CS 16              // s-rows produced per block
#define NROWS (CS + 3)     // +3 causal halo

__device__ __forceinline__ float dot4(const float4 v) {
    return fmaf(v.x, v.x, fmaf(v.y, v.y, fmaf(v.z, v.z, v.w * v.w)));
}

// ---------------------------------------------------------------------------
// Fused RMSNorm + depthwise causal conv1d (K=4) + bias. One DRAM pass over x.
// grid = (S/CS, B) = 1024 blocks, block = 512, occ 2.   [R3 structure]
// Phase 1: 16 warps compute per-row inv_rms for the 19-row window with
//          uninterrupted 16-deep LDG.128 streams.
// Phase 2: thread owns one float4 H-column, rolling 3-deep window; x re-read
//          hits L2. unroll 8 -> 8 independent loads in flight per group.
//          norm_weight folded into conv taps; streaming stores.
// ---------------------------------------------------------------------------
__global__ __launch_bounds__(512, 2) void fused_kernel(const float* __restrict__ x,
                                                       const float* __restrict__ nw,
                                                       const float* __restrict__ cw,
                                                       const float* __restrict__ cb,
                                                       float*       __restrict__ out) {
    __shared__ float s_ir[NROWS];

    const int b    = blockIdx.y;
    const int s0   = blockIdx.x * CS;
    const int tid  = threadIdx.x;
    const int warp = tid >> 5;
    const int lane = tid & 31;

    const float* xb = x   + (size_t)b * Sn * Hn;
    float*       ob = out + (size_t)b * Sn * Hn;

    // ---- Phase 1: inv_rms for rows s0-3 .. s0+CS-1 ----
    for (int j = warp; j < NROWS; j += 16) {
        const int s = s0 - 3 + j;
        float a0 = 0.f, a1 = 0.f;
        if (s >= 0) {
            const float4* xr = reinterpret_cast<const float4*>(xb + (size_t)s * Hn);
#pragma unroll
            for (int i = 0; i < 16; i += 2) {
                float4 v0 = xr[lane + 32 * (i + 0)];
                float4 v1 = xr[lane + 32 * (i + 1)];
                a0 += dot4(v0);
                a1 += dot4(v1);
            }
        }
        float ss = a0 + a1;
#pragma unroll
        for (int o = 16; o; o >>= 1)
            ss += __shfl_xor_sync(0xFFFFFFFFu, ss, o);
        if (lane == 0)
            s_ir[j] = (s >= 0) ? rsqrtf(ss * (1.0f / (float)Hn) + EPSf) : 0.0f;
    }
    __syncthreads();

    // ---- Phase 2: conv over rows s0 .. s0+CS-1, thread owns float4 column h4=tid ----
    const int h4 = tid;                 // 0..511
    const int h  = h4 * 4;

    // Taps with norm_weight folded in: (w_k * nw_h). Window then stores v*r only.
    const float4* cw4 = reinterpret_cast<const float4*>(cw);
    const float4 nwv = __ldg(&reinterpret_cast<const float4*>(nw)[h4]);
    float4 t0 = __ldg(&cw4[h + 0]);
    float4 t1 = __ldg(&cw4[h + 1]);
    float4 t2 = __ldg(&cw4[h + 2]);
    float4 t3 = __ldg(&cw4[h + 3]);
    t0.x *= nwv.x; t0.y *= nwv.x; t0.z *= nwv.x; t0.w *= nwv.x;
    t1.x *= nwv.y; t1.y *= nwv.y; t1.z *= nwv.y; t1.w *= nwv.y;
    t2.x *= nwv.z; t2.y *= nwv.z; t2.z *= nwv.z; t2.w *= nwv.z;
    t3.x *= nwv.w; t3.y *= nwv.w; t3.z *= nwv.w; t3.w *= nwv.w;
    const float4 bias = __ldg(&reinterpret_cast<const float4*>(cb)[h4]);

    // Rolling window of v*r for rows s0-3, s0-2, s0-1
    float4 xm3, xm2, xm1;
    {
        float4 pre[3];
#pragma unroll
        for (int j = 0; j < 3; j++) {
            const int s = s0 - 3 + j;
            if (s >= 0) {
                float4 v = reinterpret_cast<const float4*>(xb + (size_t)s * Hn)[h4];
                const float r = s_ir[j];
                pre[j].x = v.x * r;
                pre[j].y = v.y * r;
                pre[j].z = v.z * r;
                pre[j].w = v.w * r;
            } else {
                pre[j] = make_float4(0.f, 0.f, 0.f, 0.f);
            }
        }
        xm3 = pre[0]; xm2 = pre[1]; xm1 = pre[2];
    }

#pragma unroll 8
    for (int j = 0; j < CS; j++) {
        const int s = s0 + j;
        float4 v = reinterpret_cast<const float4*>(xb + (size_t)s * Hn)[h4];
        const float r = s_ir[j + 3];
        float4 xn;
        xn.x = v.x * r;
        xn.y = v.y * r;
        xn.z = v.z * r;
        xn.w = v.w * r;

        float4 y;
        y.x = fmaf(t0.x, xm3.x, fmaf(t0.y, xm2.x, fmaf(t0.z, xm1.x, fmaf(t0.w, xn.x, bias.x))));
        y.y = fmaf(t1.x, xm3.y, fmaf(t1.y, xm2.y, fmaf(t1.z, xm1.y, fmaf(t1.w, xn.y, bias.y))));
        y.z = fmaf(t2.x, xm3.z, fmaf(t2.y, xm2.z, fmaf(t2.z, xm1.z, fmaf(t2.w, xn.z, bias.z))));
        y.w = fmaf(t3.x, xm3.w, fmaf(t3.y, xm2.w, fmaf(t3.z, xm1.w, fmaf(t3.w, xn.w, bias.w))));

        // Streaming store: output is never re-read; don't pollute L2.
        __stcs(reinterpret_cast<float4*>(ob + (size_t)s * Hn) + h4, y);

        xm3 = xm2; xm2 = xm1; xm1 = xn;
    }
}

// ---------------------------------------------------------------------------
// Inputs (metadata order): hidden_states, norm_weight, conv_weight, conv_bias
// ---------------------------------------------------------------------------
extern "C" void kernel_launch(void* const* d_in, const int* in_sizes, int n_in,
                              void* d_out, int out_size) {
    const float* x  = (const float*)d_in[0];
    const float* nw = (const float*)d_in[1];
    const float* cw = (const float*)d_in[2];
    const float* cb = (const float*)d_in[3];
    float* out = (float*)d_out;

    dim3 grid(Sn / CS, Bn);             // (256, 4) = 1024 blocks
    fused_kernel<<<grid, 512>>>(x, nw, cw, cb, out);
}